// round 16
// baseline (speedup 1.0000x reference)
#include <cuda_runtime.h>
#include <cuda_bf16.h>
#include <cuda_fp16.h>
#include <cstdint>

#define NB 4
#define NS 1024
#define ND 1024
#define NH 16
#define NDH 64

#define E_X   ((long)NB * NS * ND)       // 4194304
#define E_W   ((long)ND * ND)            // 1048576
#define E_PE  ((long)NH * NS * NDH)      // 1048576
#define E_ATT ((long)NB * NH * NS * NS)  // 67108864

#define LOG2E 1.4426950408889634f

// Plane buffers (hi at [0,E), lo at [E,2E)), uint4-declared for 16B alignment.
__device__ uint4 p_x[E_X / 4],  p_y[E_X / 4],  p_z[E_X / 4];
__device__ uint4 p_q[E_X / 4],  p_k[E_X / 4];
__device__ uint4 p_vt[E_X / 4], p_ctx[E_X / 4];
__device__ uint4 p_wq[E_W / 4], p_wk[E_W / 4], p_wv[E_W / 4], p_wo[E_W / 4];
__device__ uint4 p_pe[E_PE / 4];
__device__ float g_pshift[E_ATT];        // shifted pos logits (log2-scaled)

// ---------------------------------------------------------------------------
// Base-ISA helpers
// ---------------------------------------------------------------------------
static __device__ __forceinline__ uint32_t smem_u32(const void* p) {
    uint32_t a;
    asm("{ .reg .u64 t; cvta.to.shared.u64 t, %1; cvt.u32.u64 %0, t; }"
        : "=r"(a) : "l"(p));
    return a;
}
static __device__ __forceinline__ void ldsm_x4(uint32_t* r, uint32_t addr) {
    asm volatile("ldmatrix.sync.aligned.m8n8.x4.shared.b16 {%0,%1,%2,%3}, [%4];"
                 : "=r"(r[0]), "=r"(r[1]), "=r"(r[2]), "=r"(r[3]) : "r"(addr));
}
// TIN: 0 = bf16 operands, 1 = fp16 operands (fp32 accum both)
template <int TIN>
static __device__ __forceinline__ void mma16(float* c, const uint32_t* a,
                                             const uint32_t* b) {
    if (TIN == 0)
        asm volatile(
            "mma.sync.aligned.m16n8k16.row.col.f32.bf16.bf16.f32 "
            "{%0,%1,%2,%3}, {%4,%5,%6,%7}, {%8,%9}, {%0,%1,%2,%3};"
            : "+f"(c[0]), "+f"(c[1]), "+f"(c[2]), "+f"(c[3])
            : "r"(a[0]), "r"(a[1]), "r"(a[2]), "r"(a[3]), "r"(b[0]), "r"(b[1]));
    else
        asm volatile(
            "mma.sync.aligned.m16n8k16.row.col.f32.f16.f16.f32 "
            "{%0,%1,%2,%3}, {%4,%5,%6,%7}, {%8,%9}, {%0,%1,%2,%3};"
            : "+f"(c[0]), "+f"(c[1]), "+f"(c[2]), "+f"(c[3])
            : "r"(a[0]), "r"(a[1]), "r"(a[2]), "r"(a[3]), "r"(b[0]), "r"(b[1]));
}
static __device__ __forceinline__ void cpa16(uint32_t d, const void* s) {
    asm volatile("cp.async.cg.shared.global [%0], [%1], 16;" :: "r"(d), "l"(s));
}
static __device__ __forceinline__ void cpa_commit() {
    asm volatile("cp.async.commit_group;" ::: "memory");
}
template <int N> static __device__ __forceinline__ void cpa_wait() {
    asm volatile("cp.async.wait_group %0;" :: "n"(N) : "memory");
}
static __device__ __forceinline__ uint32_t packhf(float x, float y) {
    __half2 t = __floats2half2_rn(x, y);
    return *(uint32_t*)&t;
}
// Single-MUFU exp2 (libm exp2f without -use_fast_math is a multi-instruction
// sequence; EX2.approx is 2^-22-accurate — far below our error floor).
static __device__ __forceinline__ float fex2(float x) {
    float r;
    asm("ex2.approx.ftz.f32 %0, %1;" : "=f"(r) : "f"(x));
    return r;
}

// ---------------------------------------------------------------------------
// GEMM: C = alpha * A @ B^T, 16-bit hi/lo planes in, split accumulation.
// MODE 0: fp32 out.
// MODE 6: merged qkv projection — z<2: fp16 hi/lo plane out (q,k; k skips the
//         never-read lo plane); z==2: fp16 single-plane transposed per-head
//         out (uses Av2/Bv2/Cv2).
// TIN: operand type (0 bf16 / 1 fp16).  ASP: A single-plane (2-MMA).
// Pipeline: one sync per K-chunk ({wait; sync; issue(next); compute}).
// ---------------------------------------------------------------------------
template <int BN, int MODE, int TIN, int ASP>
__global__ void __launch_bounds__(256, 2) gemm2(
    const void* __restrict__ Av, const void* __restrict__ Bv,
    void* __restrict__ Cv,
    const void* __restrict__ Av2, const void* __restrict__ Bv2,
    void* __restrict__ Cv2,
    int K, int lda, int ldb, int ldc,
    long aOut, long aIn, long bOut, long bIn, long cOut, long cIn,
    long aPl, long bPl, long cPl, float alpha)
{
    constexpr int BM = 128, LDE = 40;
    constexpr int WM = 2;
    constexpr int MT = (BM / WM) / 16;            // 4
    constexpr int AH = 0;
    constexpr int AL = BM * LDE * 2;
    constexpr int BH = 2 * AL;
    constexpr int BL = BH + BN * LDE * 2;
    constexpr int STAGE = BH + 2 * BN * LDE * 2;

    extern __shared__ __align__(128) char sm[];
    const uint32_t sb = smem_u32(sm);

    const int tid = threadIdx.x, wid = tid >> 5, lane = tid & 31;
    const int wm = wid % WM, wn = wid / WM;
    const int z = blockIdx.z;
    const bool alt = (MODE == 6 && z == 2);
    const int ze = alt ? 0 : z;
    const int zo = ze / NH, zi = ze % NH;

    const uint16_t* A = (const uint16_t*)(alt ? Av2 : Av);
    const uint16_t* Bp = (const uint16_t*)(alt ? Bv2 : Bv);
    const uint16_t* Ab = A + (long)zo * aOut + (long)zi * aIn
                         + (long)(blockIdx.y * BM) * lda;
    const uint16_t* Bb = Bp + (long)zo * bOut + (long)zi * bIn
                         + (long)(blockIdx.x * BN) * ldb;

    auto issue = [&](int s, int kt) {
        const uint32_t st = sb + s * STAGE;
        #pragma unroll
        for (int t = 0; t < 2; ++t) {
            int r = (tid + t * 256) >> 2, sg = tid & 3;
            const uint16_t* g = Ab + (long)r * lda + kt + sg * 8;
            uint32_t d = st + r * 80 + sg * 16;
            cpa16(d + AH, g);
            if (!ASP) cpa16(d + AL, g + aPl);
        }
        #pragma unroll
        for (int t = 0; t < BN / 64; ++t) {
            int r = (tid + t * 256) >> 2, sg = tid & 3;
            const uint16_t* g = Bb + (long)r * ldb + kt + sg * 8;
            uint32_t d = st + r * 80 + sg * 16;
            cpa16(d + BH, g);
            cpa16(d + BL, g + bPl);
        }
        cpa_commit();
    };

    const uint32_t aRelH = AH +
        (uint32_t)(((wm * MT * 16 + (lane & 15)) * LDE + (lane >> 4) * 8) * 2);
    const uint32_t aRelL = aRelH + (AL - AH);
    const int brow = (lane & 7) | ((lane >> 1) & 8);
    const uint32_t bRelH = BH +
        (uint32_t)(((wn * 32 + brow) * LDE + ((lane >> 3) & 1) * 8) * 2);
    const uint32_t bRelL = bRelH + (BL - BH);

    float acc[MT][4][4] = {};
    issue(0, 0);

    const int nch = K >> 5;
    for (int c = 0; c < nch; ++c) {
        cpa_wait<0>();
        __syncthreads();
        if (c + 1 < nch) issue((c + 1) & 1, (c + 1) << 5);
        const uint32_t s0 = sb + (c & 1) * STAGE;
        #pragma unroll
        for (int ks = 0; ks < 2; ++ks) {
            uint32_t ah[MT][4], al[MT][4], bh[2][4], bl[2][4];
            #pragma unroll
            for (int mt = 0; mt < MT; ++mt) {
                ldsm_x4(ah[mt], s0 + aRelH + mt * (16 * LDE * 2) + ks * 32);
                if (!ASP)
                    ldsm_x4(al[mt], s0 + aRelL + mt * (16 * LDE * 2) + ks * 32);
            }
            #pragma unroll
            for (int nt2 = 0; nt2 < 2; ++nt2) {
                ldsm_x4(bh[nt2], s0 + bRelH + nt2 * (16 * LDE * 2) + ks * 32);
                ldsm_x4(bl[nt2], s0 + bRelL + nt2 * (16 * LDE * 2) + ks * 32);
            }
            #pragma unroll
            for (int mt = 0; mt < MT; ++mt)
                #pragma unroll
                for (int nt = 0; nt < 4; ++nt) {
                    float* cc = acc[mt][nt];
                    const uint32_t* bhp = &bh[nt >> 1][(nt & 1) * 2];
                    const uint32_t* blp = &bl[nt >> 1][(nt & 1) * 2];
                    mma16<TIN>(cc, ah[mt], bhp);
                    mma16<TIN>(cc, ah[mt], blp);
                    if (!ASP) mma16<TIN>(cc, al[mt], bhp);
                }
        }
    }

    const int r0 = wm * (MT * 16) + (lane >> 2);
    const int c0 = wn * 32 + (lane & 3) * 2;
    if (MODE == 6) {
        if (z < 2) {
            __half* Ch = (__half*)Cv + (long)zo * cOut + (long)zi * cIn
                         + (long)(blockIdx.y * BM) * ldc + blockIdx.x * BN;
            #pragma unroll
            for (int mt = 0; mt < MT; ++mt)
                #pragma unroll
                for (int nt = 0; nt < 4; ++nt)
                    #pragma unroll
                    for (int h = 0; h < 2; ++h) {
                        long off = (long)(r0 + mt * 16 + h * 8) * ldc + c0 + nt * 8;
                        float x0 = acc[mt][nt][h * 2 + 0] * alpha;
                        float x1 = acc[mt][nt][h * 2 + 1] * alpha;
                        __half2 hi = __floats2half2_rn(x0, x1);
                        *(__half2*)(Ch + off) = hi;
                        if (z == 0) {   // k (z==1) lo plane is never read
                            __half2 lo = __floats2half2_rn(
                                x0 - __half2float(__low2half(hi)),
                                x1 - __half2float(__high2half(hi)));
                            *(__half2*)(Ch + off + cPl) = lo;
                        }
                    }
        } else {
            // Transposed per-head single-plane store -> Cv2 ([B,H,DH,S])
            __half* st = (__half*)sm;
            __syncthreads();     // other warps may still read load stages
            #pragma unroll
            for (int mt = 0; mt < MT; ++mt)
                #pragma unroll
                for (int nt = 0; nt < 4; ++nt)
                    #pragma unroll
                    for (int h = 0; h < 2; ++h) {
                        int r = r0 + mt * 16 + h * 8;
                        int c = c0 + nt * 8;
                        float x0 = acc[mt][nt][h * 2 + 0] * alpha;
                        float x1 = acc[mt][nt][h * 2 + 1] * alpha;
                        __half2 hi = __floats2half2_rn(x0, x1);
                        st[c * 136 + r]       = __low2half(hi);
                        st[(c + 1) * 136 + r] = __high2half(hi);
                    }
            __syncthreads();
            const int b = blockIdx.y >> 3, s0r = (blockIdx.y & 7) * 128;
            __half* vt = (__half*)Cv2;
            #pragma unroll
            for (int t = 0; t < 8; ++t) {
                int u = tid + t * 256;
                int c = u >> 4, rch = u & 15;
                int d = blockIdx.x * 128 + c;
                int hh = d >> 6, dh = d & 63;
                uint4 val = *(const uint4*)(st + c * 136 + rch * 8);
                *(uint4*)(vt + ((long)(b * NH + hh) * NDH + dh) * NS + s0r + rch * 8) = val;
            }
        }
    } else {  // MODE 0
        float* Cf = (float*)Cv + (long)zo * cOut + (long)zi * cIn
                    + (long)(blockIdx.y * BM) * ldc + blockIdx.x * BN;
        #pragma unroll
        for (int mt = 0; mt < MT; ++mt)
            #pragma unroll
            for (int nt = 0; nt < 4; ++nt)
                #pragma unroll
                for (int h = 0; h < 2; ++h) {
                    long off = (long)(r0 + mt * 16 + h * 8) * ldc + c0 + nt * 8;
                    float2 v = make_float2(acc[mt][nt][h * 2 + 0] * alpha,
                                           acc[mt][nt][h * 2 + 1] * alpha);
                    *(float2*)(Cf + off) = v;
                }
    }
}

// ---------------------------------------------------------------------------
// Pshift kernel (persistent-j): one CTA per (i-tile, bh). A tile (q rows,
// hi+lo, both K-chunks) loaded ONCE; loop over the by+1 active j-tiles with
// chunk-granular double-buffered pe loads. Shifted scattered stores.
// Out[i, jj-(NS-1)+i] = alpha * sum_d q[i,d]*pe[jj,d]  (only j >= 0).
// ---------------------------------------------------------------------------
constexpr int PS_A   = 0;            // 4 x 10240: c0hi, c0lo, c1hi, c1lo
constexpr int PS_B   = 40960;        // 2 stages x (hi 10240 + lo 10240)
constexpr int PS_TOT = 81920;

__global__ void __launch_bounds__(256, 2) pshift_kernel(
    const __half* __restrict__ q, const __half* __restrict__ pe,
    float* __restrict__ out)
{
    constexpr int LDE = 40;
    extern __shared__ __align__(128) char sm[];
    const uint32_t sb = smem_u32(sm);
    const int tid = threadIdx.x, wid = tid >> 5, lane = tid & 31;
    const int wm = wid & 1, wn = wid >> 1;        // 2 x 4 warp grid
    const int by = blockIdx.x;                    // i-tile 0..7
    const int bh = blockIdx.y;                    // 0..63
    const int b = bh >> 4, h = bh & 15;
    const int i0 = by * 128;
    const float ALPHA = 8.0f * LOG2E;

    const __half* qg  = q + (long)b * NS * ND + (long)i0 * ND + h * NDH;
    const __half* peg = pe + (long)h * NS * NDH;
    float* Cf = out + (long)bh * NS * NS;

    const int jmin = 7 - by;                      // active tiles: jx+by >= 7
    const int total = (by + 1) * 2;               // chunks (2 per j-tile)

    // A: both K-chunks, hi+lo (2048 cpa16)
    #pragma unroll
    for (int t = 0; t < 8; ++t) {
        int idx = tid + t * 256;
        int pc = idx >> 9;                        // chunk*2 + plane
        int rem = idx & 511;
        int r = rem >> 2, sg = rem & 3;
        int chunk = pc >> 1, plane = pc & 1;
        cpa16(sb + PS_A + pc * 10240 + r * 80 + sg * 16,
              qg + (long)plane * E_X + (long)r * ND + chunk * 32 + sg * 8);
    }
    cpa_commit();

    auto issueB = [&](int ci) {
        int jx = jmin + (ci >> 1), c = ci & 1, st = ci & 1;
        const __half* bg = peg + (long)(jx * 128) * NDH + c * 32;
        #pragma unroll
        for (int t = 0; t < 4; ++t) {
            int idx = tid + t * 256;
            int plane = idx >> 9;
            int rem = idx & 511;
            int r = rem >> 2, sg = rem & 3;
            cpa16(sb + PS_B + st * 20480 + plane * 10240 + r * 80 + sg * 16,
                  bg + (long)plane * E_PE + (long)r * NDH + sg * 8);
        }
        cpa_commit();
    };
    issueB(0);

    const uint32_t aRel =
        (uint32_t)(((wm * 64 + (lane & 15)) * LDE + (lane >> 4) * 8) * 2);
    const int brow = (lane & 7) | ((lane >> 1) & 8);
    const uint32_t bRel =
        (uint32_t)(((wn * 32 + brow) * LDE + ((lane >> 3) & 1) * 8) * 2);
    const int r0 = wm * 64 + (lane >> 2);
    const int c0l = wn * 32 + (lane & 3) * 2;

    float acc[4][4][4] = {};

    for (int ci = 0; ci < total; ++ci) {
        cpa_wait<0>();
        __syncthreads();
        if (ci + 1 < total) issueB(ci + 1);

        const int jx = jmin + (ci >> 1), c = ci & 1, st = ci & 1;
        const uint32_t Abuf = sb + PS_A + (c * 2) * 10240;  // hi; lo +10240
        const uint32_t Bbuf = sb + PS_B + st * 20480;       // hi; lo +10240

        #pragma unroll
        for (int ks = 0; ks < 2; ++ks) {
            uint32_t ah[4][4], al[4][4], bhf[2][4], blf[2][4];
            #pragma unroll
            for (int mt = 0; mt < 4; ++mt) {
                ldsm_x4(ah[mt], Abuf + aRel + mt * (16 * LDE * 2) + ks * 32);
                ldsm_x4(al[mt], Abuf + 10240 + aRel + mt * (16 * LDE * 2) + ks * 32);
            }
            #pragma unroll
            for (int nt2 = 0; nt2 < 2; ++nt2) {
                ldsm_x4(bhf[nt2], Bbuf + bRel + nt2 * (16 * LDE * 2) + ks * 32);
                ldsm_x4(blf[nt2], Bbuf + 10240 + bRel + nt2 * (16 * LDE * 2) + ks * 32);
            }
            #pragma unroll
            for (int mt = 0; mt < 4; ++mt)
                #pragma unroll
                for (int nt = 0; nt < 4; ++nt) {
                    float* cc = acc[mt][nt];
                    const uint32_t* bp = &bhf[nt >> 1][(nt & 1) * 2];
                    const uint32_t* lp = &blf[nt >> 1][(nt & 1) * 2];
                    mma16<1>(cc, ah[mt], bp);
                    mma16<1>(cc, ah[mt], lp);
                    mma16<1>(cc, al[mt], bp);
                }
        }

        if (c == 1) {  // epilogue for this j-tile: shifted scattered stores
            const int j0x = jx * 128;
            #pragma unroll
            for (int mt = 0; mt < 4; ++mt)
                #pragma unroll
                for (int h2 = 0; h2 < 2; ++h2) {
                    int ig = i0 + r0 + mt * 16 + h2 * 8;
                    #pragma unroll
                    for (int nt = 0; nt < 4; ++nt) {
                        int j = j0x + c0l + nt * 8 - (NS - 1) + ig;
                        float x0 = acc[mt][nt][h2 * 2 + 0] * ALPHA;
                        float x1 = acc[mt][nt][h2 * 2 + 1] * ALPHA;
                        if (j >= 0)     Cf[(long)ig * NS + j]     = x0;
                        if (j + 1 >= 0) Cf[(long)ig * NS + j + 1] = x1;
                    }
                }
            #pragma unroll
            for (int mt = 0; mt < 4; ++mt)
                #pragma unroll
                for (int nt = 0; nt < 4; ++nt)
                    #pragma unroll
                    for (int u = 0; u < 4; ++u) acc[mt][nt][u] = 0.0f;
        }
    }
}

// ---------------------------------------------------------------------------
// Fused attention, lean precision: QK = qh*kh (1 MMA), AV = P*Vh (1 MMA).
// Online softmax (base-2) with single-MUFU EX2. One sync per j-tile.
// lA/lB quad-reduced inside the loop; no further reduction in the epilogue.
// ---------------------------------------------------------------------------
constexpr int G_KS = 9216;                       // 64 x 72 fp16 stage
constexpr int G_K  = 0;                          // 2 stages -> [0, 18432)
constexpr int G_V  = 18432;                      // 2 stages -> [18432, 36864)
constexpr int G_MB = 36864;                      // mask bias -> [36864, 40960)
constexpr int G_P  = 40960;                      // 2 stages x 34816 -> 110592
constexpr int G_PST = 34816;
constexpr int G_TOT = 110592;

__global__ void __launch_bounds__(256, 2) fused_attn(
    const __half* __restrict__ q, const __half* __restrict__ k,
    const __half* __restrict__ vt, const float* __restrict__ pshift,
    const int* __restrict__ mask, __half* __restrict__ ctx)
{
    extern __shared__ __align__(128) char sm[];
    const uint32_t sb = smem_u32(sm);
    const int tid = threadIdx.x, wid = tid >> 5, lane = tid & 31;
    const int i0 = (7 - blockIdx.x) * 128;       // heavy-first
    const int bh = blockIdx.y, b = bh / NH, h = bh % NH;
    const float SC = 0.125f * LOG2E;

    const __half* qg  = q + (long)b * NS * ND + (long)i0 * ND + h * NDH;
    const __half* kg  = k + (long)b * NS * ND + h * NDH;
    const __half* vtg = vt + (long)bh * NDH * NS;
    const float* pg = pshift + (long)bh * NS * NS + (long)i0 * NS;

    float* mbias = (float*)(sm + G_MB);
    for (int j = tid; j < NS; j += 256)
        mbias[j] = mask[b * NS + j] ? 0.0f : -1.5e9f;

    // ---- Prologue: Q hi plane through the K area, consume to registers ----
    #pragma unroll
    for (int t = 0; t < 4; ++t) {
        int idx = tid + t * 256;
        int r = idx >> 3, ch = idx & 7;
        cpa16(sb + (r * 72 + ch * 8) * 2, qg + (long)r * ND + ch * 8);
    }
    cpa_commit();
    cpa_wait<0>();
    __syncthreads();

    uint32_t qah[4][4];
    {
        uint32_t base = sb + ((wid * 16 + (lane & 15)) * 72 + (lane >> 4) * 8) * 2;
        #pragma unroll
        for (int kt = 0; kt < 4; ++kt) ldsm_x4(qah[kt], base + kt * 32);
    }
    __syncthreads();     // Q fully consumed; K area free for reuse

    auto issue = [&](int jt) {
        const int st = jt & 1, j0 = jt * 64;
        #pragma unroll
        for (int t = 0; t < 2; ++t) {   // K hi tile
            int idx = tid + t * 256;
            int r = idx >> 3, ch = idx & 7;
            cpa16(sb + G_K + st * G_KS + (r * 72 + ch * 8) * 2,
                  kg + (long)(j0 + r) * ND + ch * 8);
        }
        #pragma unroll
        for (int t = 0; t < 2; ++t) {   // V hi tile
            int idx = tid + t * 256;
            int d = idx >> 3, ch = idx & 7;
            cpa16(sb + G_V + st * G_KS + (d * 72 + ch * 8) * 2,
                  vtg + (long)d * NS + j0 + ch * 8);
        }
        if (j0 <= i0 + 127) {           // Pshift tile (fp32)
            #pragma unroll
            for (int t = 0; t < 8; ++t) {
                int idx = tid + t * 256;
                int r = idx >> 4, ch = idx & 15;
                cpa16(sb + G_P + st * G_PST + (r * 68 + ch * 4) * 4,
                      pg + (long)r * NS + j0 + ch * 4);
            }
        }
        cpa_commit();
    };

    issue(0);

    const int rA = wid * 16 + (lane >> 2);
    const int iA = i0 + rA, iB = iA + 8;
    const int miA = mask[b * NS + iA], miB = mask[b * NS + iB];
    const int brow = (lane & 7) | ((lane >> 1) & 8);
    const int bcol = ((lane >> 3) & 1) * 8;

    float oacc[8][4] = {};
    float mA = -1.0e30f, mB = -1.0e30f, lA = 0.0f, lB = 0.0f;

    for (int jt = 0; jt < 16; ++jt) {
        cpa_wait<0>();
        __syncthreads();
        if (jt + 1 < 16) issue(jt + 1);

        const int st = jt & 1, j0 = jt * 64;
        const uint32_t kb = sb + G_K + st * G_KS;
        const uint32_t vb = sb + G_V + st * G_KS;
        const bool anyP = (j0 <= i0 + 127);
        const float* psm = (const float*)(sm + G_P + st * G_PST);

        // ---- S = qh @ kh^T (1 MMA) ----
        float sacc[8][4] = {};
        #pragma unroll
        for (int kt = 0; kt < 4; ++kt) {
            uint32_t bhf[4][4];
            #pragma unroll
            for (int p = 0; p < 4; ++p)
                ldsm_x4(bhf[p], kb + ((p * 16 + brow) * 72 + bcol + kt * 16) * 2);
            #pragma unroll
            for (int nt = 0; nt < 8; ++nt)
                mma16<1>(sacc[nt], qah[kt], &bhf[nt >> 1][(nt & 1) * 2]);
        }

        // ---- logits (log2 domain): scale + pshift + mask ----
        #pragma unroll
        for (int nt = 0; nt < 8; ++nt) {
            int jl = nt * 8 + (lane & 3) * 2;
            int jg = j0 + jl;
            float p0A = 0, p1A = 0, p0B = 0, p1B = 0;
            if (anyP) {
                float2 fa = *(const float2*)(psm + rA * 68 + jl);
                float2 fb = *(const float2*)(psm + (rA + 8) * 68 + jl);
                p0A = (jg     <= iA) ? fa.x : 0.0f;
                p1A = (jg + 1 <= iA) ? fa.y : 0.0f;
                p0B = (jg     <= iB) ? fb.x : 0.0f;
                p1B = (jg + 1 <= iB) ? fb.y : 0.0f;
            }
            float b0 = mbias[jg], b1 = mbias[jg + 1];
            sacc[nt][0] = miA ? fmaf(sacc[nt][0], SC, p0A) + b0 : -1.0e9f;
            sacc[nt][1] = miA ? fmaf(sacc[nt][1], SC, p1A) + b1 : -1.0e9f;
            sacc[nt][2] = miB ? fmaf(sacc[nt][2], SC, p0B) + b0 : -1.0e9f;
            sacc[nt][3] = miB ? fmaf(sacc[nt][3], SC, p1B) + b1 : -1.0e9f;
        }

        // ---- online softmax (base-2, single-MUFU EX2) ----
        float rmA = -1.0e30f, rmB = -1.0e30f;
        #pragma unroll
        for (int nt = 0; nt < 8; ++nt) {
            rmA = fmaxf(rmA, fmaxf(sacc[nt][0], sacc[nt][1]));
            rmB = fmaxf(rmB, fmaxf(sacc[nt][2], sacc[nt][3]));
        }
        rmA = fmaxf(rmA, __shfl_xor_sync(0xffffffffu, rmA, 1));
        rmA = fmaxf(rmA, __shfl_xor_sync(0xffffffffu, rmA, 2));
        rmB = fmaxf(rmB, __shfl_xor_sync(0xffffffffu, rmB, 1));
        rmB = fmaxf(rmB, __shfl_xor_sync(0xffffffffu, rmB, 2));

        float mnA = fmaxf(mA, rmA), mnB = fmaxf(mB, rmB);
        float alA = fex2(mA - mnA), alB = fex2(mB - mnB);
        mA = mnA; mB = mnB;

        float rsA = 0.0f, rsB = 0.0f;
        #pragma unroll
        for (int nt = 0; nt < 8; ++nt) {
            sacc[nt][0] = fex2(sacc[nt][0] - mnA);
            sacc[nt][1] = fex2(sacc[nt][1] - mnA);
            sacc[nt][2] = fex2(sacc[nt][2] - mnB);
            sacc[nt][3] = fex2(sacc[nt][3] - mnB);
            rsA += sacc[nt][0] + sacc[nt][1];
            rsB += sacc[nt][2] + sacc[nt][3];
        }
        rsA += __shfl_xor_sync(0xffffffffu, rsA, 1);
        rsA += __shfl_xor_sync(0xffffffffu, rsA, 2);
        rsB += __shfl_xor_sync(0xffffffffu, rsB, 1);
        rsB += __shfl_xor_sync(0xffffffffu, rsB, 2);
        lA = lA * alA + rsA;
        lB = lB * alB + rsB;
        #pragma unroll
        for (int nt = 0; nt < 8; ++nt) {
            oacc[nt][0] *= alA; oacc[nt][1] *= alA;
            oacc[nt][2] *= alB; oacc[nt][3] *= alB;
        }

        // ---- pack P into fp16 A-fragments ----
        uint32_t pah[4][4];
        #pragma unroll
        for (int kt = 0; kt < 4; ++kt) {
            const float* e = sacc[2 * kt];
            const float* o = sacc[2 * kt + 1];
            pah[kt][0] = packhf(e[0], e[1]); pah[kt][1] = packhf(e[2], e[3]);
            pah[kt][2] = packhf(o[0], o[1]); pah[kt][3] = packhf(o[2], o[3]);
        }

        // ---- O += P @ Vh (1 MMA) ----
        #pragma unroll
        for (int kt = 0; kt < 4; ++kt) {
            uint32_t vhf[4][4];
            #pragma unroll
            for (int p = 0; p < 4; ++p)
                ldsm_x4(vhf[p], vb + ((p * 16 + brow) * 72 + bcol + kt * 16) * 2);
            #pragma unroll
            for (int nt = 0; nt < 8; ++nt)
                mma16<1>(oacc[nt], pah[kt], &vhf[nt >> 1][(nt & 1) * 2]);
        }
    }

    // ---- epilogue (lA/lB already fully reduced in-loop) ----
    const float ivA = 1.0f / fmaxf(lA, 1e-30f);
    const float ivB = 1.0f / fmaxf(lB, 1e-30f);

    __syncthreads();     // other warps may still read stage smem
    __half* so = (__half*)sm;
    #pragma unroll
    for (int nt = 0; nt < 8; ++nt) {
        int c = nt * 8 + (lane & 3) * 2;
        *(__half2*)(so + rA * 72 + c) =
            __floats2half2_rn(oacc[nt][0] * ivA, oacc[nt][1] * ivA);
        *(__half2*)(so + (rA + 8) * 72 + c) =
            __floats2half2_rn(oacc[nt][2] * ivB, oacc[nt][3] * ivB);
    }
    __syncthreads();
    __half* cgb = ctx + (long)b * NS * ND + (long)i0 * ND + h * NDH;
    #pragma unroll
    for (int t = 0; t < 4; ++t) {
        int idx = tid + t * 256;
        int r = idx >> 3, ch = idx & 7;
        uint4 val = *(const uint4*)(so + r * 72 + ch * 8);
        *(uint4*)(cgb + (long)r * ND + ch * 8) = val;
    }
}

// ---------------------------------------------------------------------------
// Merged split: fp32 -> 16-bit hi/lo planes (bf16, or fp16 when f16[seg]=1)
// ---------------------------------------------------------------------------
struct SplitArgs {
    const float4* s[8];
    uint16_t* d[8];
    int n4[8];
    int f16[8];
};
__global__ void __launch_bounds__(256) split_all(SplitArgs a)
{
    const int seg = blockIdx.y;
    const int n4 = a.n4[seg];
    const float4* s = a.s[seg];
    uint16_t* dst = a.d[seg];
    const long pl = (long)n4 * 4;
    const bool f16 = a.f16[seg] != 0;
    for (int i = blockIdx.x * 256 + threadIdx.x; i < n4; i += gridDim.x * 256) {
        float4 x = s[i];
        uint32_t h0, h1, l0, l1;
        if (f16) {
            __half2 a0 = __floats2half2_rn(x.x, x.y);
            __half2 a1 = __floats2half2_rn(x.z, x.w);
            __half2 b0 = __floats2half2_rn(x.x - __half2float(__low2half(a0)),
                                           x.y - __half2float(__high2half(a0)));
            __half2 b1 = __floats2half2_rn(x.z - __half2float(__low2half(a1)),
                                           x.w - __half2float(__high2half(a1)));
            h0 = *(uint32_t*)&a0; h1 = *(uint32_t*)&a1;
            l0 = *(uint32_t*)&b0; l1 = *(uint32_t*)&b1;
        } else {
            __nv_bfloat162 a0 = __floats2bfloat162_rn(x.x, x.y);
            __nv_bfloat162 a1 = __floats2bfloat162_rn(x.z, x.w);
            __nv_bfloat162 b0 = __floats2bfloat162_rn(x.x - __low2float(a0),
                                                      x.y - __high2float(a0));
            __nv_bfloat162 b1 = __floats2bfloat162_rn(x.z - __low2float(a1),
                                                      x.w - __high2float(a1));
            h0 = *(uint32_t*)&a0; h1 = *(uint32_t*)&a1;
            l0 = *(uint32_t*)&b0; l1 = *(uint32_t*)&b1;
        }
        ((uint32_t*)dst)[2 * i]          = h0;
        ((uint32_t*)dst)[2 * i + 1]      = h1;
        ((uint32_t*)(dst + pl))[2 * i]     = l0;
        ((uint32_t*)(dst + pl))[2 * i + 1] = l1;
    }
}

// ---------------------------------------------------------------------------
extern "C" void kernel_launch(void* const* d_in, const int* in_sizes, int n_in,
                              void* d_out, int out_size)
{
    const float* query = (const float*)d_in[0];
    const float* key   = (const float*)d_in[1];
    const float* value = (const float*)d_in[2];
    const int*   mask  = (const int*)  d_in[3];
    const float* pe    = (const float*)d_in[4];
    const float* Wq    = (const float*)d_in[5];
    const float* Wk    = (const float*)d_in[6];
    const float* Wv    = (const float*)d_in[7];
    const float* Wo    = (const float*)d_in[8];
    float* out = (float*)d_out;

    void *vx, *vy, *vz, *vq, *vk, *vvt, *vctx, *vwq, *vwk, *vwv, *vwo,
         *vpe, *vps;
    cudaGetSymbolAddress(&vx, p_x);     cudaGetSymbolAddress(&vy, p_y);
    cudaGetSymbolAddress(&vz, p_z);     cudaGetSymbolAddress(&vq, p_q);
    cudaGetSymbolAddress(&vk, p_k);     cudaGetSymbolAddress(&vvt, p_vt);
    cudaGetSymbolAddress(&vctx, p_ctx);
    cudaGetSymbolAddress(&vwq, p_wq);   cudaGetSymbolAddress(&vwk, p_wk);
    cudaGetSymbolAddress(&vwv, p_wv);   cudaGetSymbolAddress(&vwo, p_wo);
    cudaGetSymbolAddress(&vpe, p_pe);   cudaGetSymbolAddress(&vps, g_pshift);

    SplitArgs sa;
    sa.s[0] = (const float4*)query; sa.d[0] = (uint16_t*)vx;  sa.n4[0] = (int)(E_X / 4);  sa.f16[0] = 0;
    sa.s[1] = (const float4*)key;   sa.d[1] = (uint16_t*)vy;  sa.n4[1] = (int)(E_X / 4);  sa.f16[1] = 0;
    sa.s[2] = (const float4*)value; sa.d[2] = (uint16_t*)vz;  sa.n4[2] = (int)(E_X / 4);  sa.f16[2] = 0;
    sa.s[3] = (const float4*)Wq;    sa.d[3] = (uint16_t*)vwq; sa.n4[3] = (int)(E_W / 4);  sa.f16[3] = 0;
    sa.s[4] = (const float4*)Wk;    sa.d[4] = (uint16_t*)vwk; sa.n4[4] = (int)(E_W / 4);  sa.f16[4] = 0;
    sa.s[5] = (const float4*)Wv;    sa.d[5] = (uint16_t*)vwv; sa.n4[5] = (int)(E_W / 4);  sa.f16[5] = 0;
    sa.s[6] = (const float4*)Wo;    sa.d[6] = (uint16_t*)vwo; sa.n4[6] = (int)(E_W / 4);  sa.f16[6] = 1;
    sa.s[7] = (const float4*)pe;    sa.d[7] = (uint16_t*)vpe; sa.n4[7] = (int)(E_PE / 4); sa.f16[7] = 1;
    split_all<<<dim3(1024, 8), 256>>>(sa);

    const int SM128 = 2 * (20480 + 2 * 128 * 80);  // 81920
    cudaFuncSetAttribute(gemm2<128, 0, 1, 1>, cudaFuncAttributeMaxDynamicSharedMemorySize, SM128);
    cudaFuncSetAttribute(gemm2<128, 6, 0, 0>, cudaFuncAttributeMaxDynamicSharedMemorySize, SM128);
    cudaFuncSetAttribute(pshift_kernel, cudaFuncAttributeMaxDynamicSharedMemorySize, PS_TOT);
    cudaFuncSetAttribute(fused_attn, cudaFuncAttributeMaxDynamicSharedMemorySize, G_TOT);

    const dim3 th(256);

    // q,k,v projections merged: z<2 -> plane out (q,k); z==2 -> transposed vt
    const long dA = (long)(((char*)vy - (char*)vx) / 2);
    const long dB = (long)(((char*)vwk - (char*)vwq) / 2);
    const long dC = (long)(((char*)vk - (char*)vq) / 2);
    gemm2<128, 6, 0, 0><<<dim3(8, 32, 3), th, SM128>>>(
        vx, vwq, vq, vz, vwv, vvt,
        ND, ND, ND, ND,
        0, dA, 0, dB, 0, dC, E_X, E_W, E_X, 1.0f);

    // Pshift: persistent-j kernel (A tile loaded once per CTA)
    pshift_kernel<<<dim3(8, NB * NH), th, PS_TOT>>>(
        (const __half*)vq, (const __half*)vpe, (float*)vps);

    // fused: QK^T + skew + mask + softmax + AV -> ctx (single fp16 plane)
    fused_attn<<<dim3(8, NB * NH), th, G_TOT>>>(
        (const __half*)vq, (const __half*)vk, (const __half*)vvt,
        (const float*)vps, mask, (__half*)vctx);

    // out = ctx(fp16, single plane) @ Wo(fp16 hi/lo)^T  -- 2-MMA
    gemm2<128, 0, 1, 1><<<dim3(8, 32, 1), th, SM128>>>(
        vctx, vwo, out, nullptr, nullptr, nullptr,
        ND, ND, ND, ND,
        0, 0, 0, 0, 0, 0, 0, E_W, 0, 1.0f);
}

// round 17
// speedup vs baseline: 1.0921x; 1.0921x over previous
#include <cuda_runtime.h>
#include <cuda_bf16.h>
#include <cuda_fp16.h>
#include <cstdint>

#define NB 4
#define NS 1024
#define ND 1024
#define NH 16
#define NDH 64

#define E_X   ((long)NB * NS * ND)       // 4194304
#define E_W   ((long)ND * ND)            // 1048576
#define E_PE  ((long)NH * NS * NDH)      // 1048576
#define E_ATT ((long)NB * NH * NS * NS)  // 67108864

#define LOG2E 1.4426950408889634f

// Plane buffers (hi at [0,E), lo at [E,2E)), uint4-declared for 16B alignment.
__device__ uint4 p_x[E_X / 4],  p_y[E_X / 4],  p_z[E_X / 4];
__device__ uint4 p_q[E_X / 4],  p_k[E_X / 4];
__device__ uint4 p_vt[E_X / 4], p_ctx[E_X / 4];
__device__ uint4 p_wq[E_W / 4], p_wk[E_W / 4], p_wv[E_W / 4], p_wo[E_W / 4];
__device__ uint4 p_pe[E_PE / 4];
__device__ float g_pshift[E_ATT];        // shifted pos logits (log2-scaled)

// ---------------------------------------------------------------------------
// Base-ISA helpers
// ---------------------------------------------------------------------------
static __device__ __forceinline__ uint32_t smem_u32(const void* p) {
    uint32_t a;
    asm("{ .reg .u64 t; cvta.to.shared.u64 t, %1; cvt.u32.u64 %0, t; }"
        : "=r"(a) : "l"(p));
    return a;
}
static __device__ __forceinline__ void ldsm_x4(uint32_t* r, uint32_t addr) {
    asm volatile("ldmatrix.sync.aligned.m8n8.x4.shared.b16 {%0,%1,%2,%3}, [%4];"
                 : "=r"(r[0]), "=r"(r[1]), "=r"(r[2]), "=r"(r[3]) : "r"(addr));
}
// TIN: 0 = bf16 operands, 1 = fp16 operands (fp32 accum both)
template <int TIN>
static __device__ __forceinline__ void mma16(float* c, const uint32_t* a,
                                             const uint32_t* b) {
    if (TIN == 0)
        asm volatile(
            "mma.sync.aligned.m16n8k16.row.col.f32.bf16.bf16.f32 "
            "{%0,%1,%2,%3}, {%4,%5,%6,%7}, {%8,%9}, {%0,%1,%2,%3};"
            : "+f"(c[0]), "+f"(c[1]), "+f"(c[2]), "+f"(c[3])
            : "r"(a[0]), "r"(a[1]), "r"(a[2]), "r"(a[3]), "r"(b[0]), "r"(b[1]));
    else
        asm volatile(
            "mma.sync.aligned.m16n8k16.row.col.f32.f16.f16.f32 "
            "{%0,%1,%2,%3}, {%4,%5,%6,%7}, {%8,%9}, {%0,%1,%2,%3};"
            : "+f"(c[0]), "+f"(c[1]), "+f"(c[2]), "+f"(c[3])
            : "r"(a[0]), "r"(a[1]), "r"(a[2]), "r"(a[3]), "r"(b[0]), "r"(b[1]));
}
static __device__ __forceinline__ void cpa16(uint32_t d, const void* s) {
    asm volatile("cp.async.cg.shared.global [%0], [%1], 16;" :: "r"(d), "l"(s));
}
static __device__ __forceinline__ void cpa_commit() {
    asm volatile("cp.async.commit_group;" ::: "memory");
}
template <int N> static __device__ __forceinline__ void cpa_wait() {
    asm volatile("cp.async.wait_group %0;" :: "n"(N) : "memory");
}
static __device__ __forceinline__ uint32_t packhf(float x, float y) {
    __half2 t = __floats2half2_rn(x, y);
    return *(uint32_t*)&t;
}
// Single-MUFU exp2 (libm exp2f without -use_fast_math is a multi-instruction
// sequence; EX2.approx is 2^-22-accurate — far below our error floor).
static __device__ __forceinline__ float fex2(float x) {
    float r;
    asm("ex2.approx.ftz.f32 %0, %1;" : "=f"(r) : "f"(x));
    return r;
}

// ---------------------------------------------------------------------------
// GEMM: C = alpha * A @ B^T, 16-bit hi/lo planes in, split accumulation.
// MODE 0: fp32 out.
// MODE 2: shifted fp32 out (skew), smem-staged coalesced per-row stores.
// MODE 6: merged qkv projection — z<2: fp16 hi/lo plane out (q; k skips the
//         never-read lo plane); z==2: fp16 single-plane transposed per-head
//         out (uses Av2/Bv2/Cv2).
// TIN: operand type (0 bf16 / 1 fp16).  ASP: A single-plane (2-MMA).
// Pipeline: one sync per K-chunk ({wait; sync; issue(next); compute}).
// ---------------------------------------------------------------------------
template <int BN, int MODE, int TIN, int ASP>
__global__ void __launch_bounds__(256, 2) gemm2(
    const void* __restrict__ Av, const void* __restrict__ Bv,
    void* __restrict__ Cv,
    const void* __restrict__ Av2, const void* __restrict__ Bv2,
    void* __restrict__ Cv2,
    int K, int lda, int ldb, int ldc,
    long aOut, long aIn, long bOut, long bIn, long cOut, long cIn,
    long aPl, long bPl, long cPl, float alpha, int tri)
{
    constexpr int BM = 128, LDE = 40;
    constexpr int WM = 2;
    constexpr int MT = (BM / WM) / 16;            // 4
    constexpr int AH = 0;
    constexpr int AL = BM * LDE * 2;
    constexpr int BH = 2 * AL;
    constexpr int BL = BH + BN * LDE * 2;
    constexpr int STAGE = BH + 2 * BN * LDE * 2;

    if (tri && (int)(blockIdx.x * BN + blockIdx.y * BM) + 255 < NS) return;

    extern __shared__ __align__(128) char sm[];
    const uint32_t sb = smem_u32(sm);

    const int tid = threadIdx.x, wid = tid >> 5, lane = tid & 31;
    const int wm = wid % WM, wn = wid / WM;
    const int z = blockIdx.z;
    const bool alt = (MODE == 6 && z == 2);
    const int ze = alt ? 0 : z;
    const int zo = ze / NH, zi = ze % NH;

    const uint16_t* A = (const uint16_t*)(alt ? Av2 : Av);
    const uint16_t* Bp = (const uint16_t*)(alt ? Bv2 : Bv);
    const uint16_t* Ab = A + (long)zo * aOut + (long)zi * aIn
                         + (long)(blockIdx.y * BM) * lda;
    const uint16_t* Bb = Bp + (long)zo * bOut + (long)zi * bIn
                         + (long)(blockIdx.x * BN) * ldb;

    auto issue = [&](int s, int kt) {
        const uint32_t st = sb + s * STAGE;
        #pragma unroll
        for (int t = 0; t < 2; ++t) {
            int r = (tid + t * 256) >> 2, sg = tid & 3;
            const uint16_t* g = Ab + (long)r * lda + kt + sg * 8;
            uint32_t d = st + r * 80 + sg * 16;
            cpa16(d + AH, g);
            if (!ASP) cpa16(d + AL, g + aPl);
        }
        #pragma unroll
        for (int t = 0; t < BN / 64; ++t) {
            int r = (tid + t * 256) >> 2, sg = tid & 3;
            const uint16_t* g = Bb + (long)r * ldb + kt + sg * 8;
            uint32_t d = st + r * 80 + sg * 16;
            cpa16(d + BH, g);
            cpa16(d + BL, g + bPl);
        }
        cpa_commit();
    };

    const uint32_t aRelH = AH +
        (uint32_t)(((wm * MT * 16 + (lane & 15)) * LDE + (lane >> 4) * 8) * 2);
    const uint32_t aRelL = aRelH + (AL - AH);
    const int brow = (lane & 7) | ((lane >> 1) & 8);
    const uint32_t bRelH = BH +
        (uint32_t)(((wn * 32 + brow) * LDE + ((lane >> 3) & 1) * 8) * 2);
    const uint32_t bRelL = bRelH + (BL - BH);

    float acc[MT][4][4] = {};
    issue(0, 0);

    const int nch = K >> 5;
    for (int c = 0; c < nch; ++c) {
        cpa_wait<0>();
        __syncthreads();
        if (c + 1 < nch) issue((c + 1) & 1, (c + 1) << 5);
        const uint32_t s0 = sb + (c & 1) * STAGE;
        #pragma unroll
        for (int ks = 0; ks < 2; ++ks) {
            uint32_t ah[MT][4], al[MT][4], bh[2][4], bl[2][4];
            #pragma unroll
            for (int mt = 0; mt < MT; ++mt) {
                ldsm_x4(ah[mt], s0 + aRelH + mt * (16 * LDE * 2) + ks * 32);
                if (!ASP)
                    ldsm_x4(al[mt], s0 + aRelL + mt * (16 * LDE * 2) + ks * 32);
            }
            #pragma unroll
            for (int nt2 = 0; nt2 < 2; ++nt2) {
                ldsm_x4(bh[nt2], s0 + bRelH + nt2 * (16 * LDE * 2) + ks * 32);
                ldsm_x4(bl[nt2], s0 + bRelL + nt2 * (16 * LDE * 2) + ks * 32);
            }
            #pragma unroll
            for (int mt = 0; mt < MT; ++mt)
                #pragma unroll
                for (int nt = 0; nt < 4; ++nt) {
                    float* cc = acc[mt][nt];
                    const uint32_t* bhp = &bh[nt >> 1][(nt & 1) * 2];
                    const uint32_t* blp = &bl[nt >> 1][(nt & 1) * 2];
                    mma16<TIN>(cc, ah[mt], bhp);
                    mma16<TIN>(cc, ah[mt], blp);
                    if (!ASP) mma16<TIN>(cc, al[mt], bhp);
                }
        }
    }

    const int r0 = wm * (MT * 16) + (lane >> 2);
    const int c0 = wn * 32 + (lane & 3) * 2;
    if (MODE == 6) {
        if (z < 2) {
            __half* Ch = (__half*)Cv + (long)zo * cOut + (long)zi * cIn
                         + (long)(blockIdx.y * BM) * ldc + blockIdx.x * BN;
            #pragma unroll
            for (int mt = 0; mt < MT; ++mt)
                #pragma unroll
                for (int nt = 0; nt < 4; ++nt)
                    #pragma unroll
                    for (int h = 0; h < 2; ++h) {
                        long off = (long)(r0 + mt * 16 + h * 8) * ldc + c0 + nt * 8;
                        float x0 = acc[mt][nt][h * 2 + 0] * alpha;
                        float x1 = acc[mt][nt][h * 2 + 1] * alpha;
                        __half2 hi = __floats2half2_rn(x0, x1);
                        *(__half2*)(Ch + off) = hi;
                        if (z == 0) {   // k (z==1) lo plane is never read
                            __half2 lo = __floats2half2_rn(
                                x0 - __half2float(__low2half(hi)),
                                x1 - __half2float(__high2half(hi)));
                            *(__half2*)(Ch + off + cPl) = lo;
                        }
                    }
        } else {
            // Transposed per-head single-plane store -> Cv2 ([B,H,DH,S])
            __half* st = (__half*)sm;
            __syncthreads();     // other warps may still read load stages
            #pragma unroll
            for (int mt = 0; mt < MT; ++mt)
                #pragma unroll
                for (int nt = 0; nt < 4; ++nt)
                    #pragma unroll
                    for (int h = 0; h < 2; ++h) {
                        int r = r0 + mt * 16 + h * 8;
                        int c = c0 + nt * 8;
                        float x0 = acc[mt][nt][h * 2 + 0] * alpha;
                        float x1 = acc[mt][nt][h * 2 + 1] * alpha;
                        __half2 hi = __floats2half2_rn(x0, x1);
                        st[c * 136 + r]       = __low2half(hi);
                        st[(c + 1) * 136 + r] = __high2half(hi);
                    }
            __syncthreads();
            const int b = blockIdx.y >> 3, s0r = (blockIdx.y & 7) * 128;
            __half* vt = (__half*)Cv2;
            #pragma unroll
            for (int t = 0; t < 8; ++t) {
                int u = tid + t * 256;
                int c = u >> 4, rch = u & 15;
                int d = blockIdx.x * 128 + c;
                int hh = d >> 6, dh = d & 63;
                uint4 val = *(const uint4*)(st + c * 136 + rch * 8);
                *(uint4*)(vt + ((long)(b * NH + hh) * NDH + dh) * NS + s0r + rch * 8) = val;
            }
        }
    } else if (MODE == 0) {
        float* Cf = (float*)Cv + (long)zo * cOut + (long)zi * cIn
                    + (long)(blockIdx.y * BM) * ldc + blockIdx.x * BN;
        #pragma unroll
        for (int mt = 0; mt < MT; ++mt)
            #pragma unroll
            for (int nt = 0; nt < 4; ++nt)
                #pragma unroll
                for (int h = 0; h < 2; ++h) {
                    long off = (long)(r0 + mt * 16 + h * 8) * ldc + c0 + nt * 8;
                    float2 v = make_float2(acc[mt][nt][h * 2 + 0] * alpha,
                                           acc[mt][nt][h * 2 + 1] * alpha);
                    *(float2*)(Cf + off) = v;
                }
    } else {  // MODE 2: shifted store via smem staging -> coalesced rows
        float* stf = (float*)sm;       // 128 x 132 fp32 = 67584 B
        __syncthreads();               // protect load stages before reuse
        #pragma unroll
        for (int mt = 0; mt < MT; ++mt)
            #pragma unroll
            for (int nt = 0; nt < 4; ++nt)
                #pragma unroll
                for (int h = 0; h < 2; ++h) {
                    int r = r0 + mt * 16 + h * 8;
                    int c = c0 + nt * 8;
                    stf[r * 132 + c]     = acc[mt][nt][h * 2 + 0] * alpha;
                    stf[r * 132 + c + 1] = acc[mt][nt][h * 2 + 1] * alpha;
                }
        __syncthreads();
        float* Cf = (float*)Cv + (long)zo * cOut + (long)zi * cIn;
        const int ig0 = blockIdx.y * BM, cg0 = blockIdx.x * BN;
        #pragma unroll
        for (int t = 0; t < 64; ++t) {
            int idx = tid + t * 256;
            int r = idx >> 7, c = idx & 127;
            int ig = ig0 + r;
            int j = cg0 + c - (NS - 1) + ig;
            if (j >= 0) Cf[(long)ig * NS + j] = stf[r * 132 + c];
        }
    }
}

// ---------------------------------------------------------------------------
// Fused attention, lean precision: QK = qh*kh (1 MMA), AV = P*Vh (1 MMA).
// Online softmax (base-2) with single-MUFU EX2. One sync per j-tile.
// lA/lB are quad-reduced INSIDE the loop -> no further epilogue reduction.
// ---------------------------------------------------------------------------
constexpr int G_KS = 9216;                       // 64 x 72 fp16 stage
constexpr int G_K  = 0;                          // 2 stages -> [0, 18432)
constexpr int G_V  = 18432;                      // 2 stages -> [18432, 36864)
constexpr int G_MB = 36864;                      // mask bias -> [36864, 40960)
constexpr int G_P  = 40960;                      // 2 stages x 34816 -> 110592
constexpr int G_PST = 34816;
constexpr int G_TOT = 110592;

__global__ void __launch_bounds__(256, 2) fused_attn(
    const __half* __restrict__ q, const __half* __restrict__ k,
    const __half* __restrict__ vt, const float* __restrict__ pshift,
    const int* __restrict__ mask, __half* __restrict__ ctx)
{
    extern __shared__ __align__(128) char sm[];
    const uint32_t sb = smem_u32(sm);
    const int tid = threadIdx.x, wid = tid >> 5, lane = tid & 31;
    const int i0 = (7 - blockIdx.x) * 128;       // heavy-first
    const int bh = blockIdx.y, b = bh / NH, h = bh % NH;
    const float SC = 0.125f * LOG2E;

    const __half* qg  = q + (long)b * NS * ND + (long)i0 * ND + h * NDH;
    const __half* kg  = k + (long)b * NS * ND + h * NDH;
    const __half* vtg = vt + (long)bh * NDH * NS;
    const float* pg = pshift + (long)bh * NS * NS + (long)i0 * NS;

    float* mbias = (float*)(sm + G_MB);
    for (int j = tid; j < NS; j += 256)
        mbias[j] = mask[b * NS + j] ? 0.0f : -1.5e9f;

    // ---- Prologue: Q hi plane through the K area, consume to registers ----
    #pragma unroll
    for (int t = 0; t < 4; ++t) {
        int idx = tid + t * 256;
        int r = idx >> 3, ch = idx & 7;
        cpa16(sb + (r * 72 + ch * 8) * 2, qg + (long)r * ND + ch * 8);
    }
    cpa_commit();
    cpa_wait<0>();
    __syncthreads();

    uint32_t qah[4][4];
    {
        uint32_t base = sb + ((wid * 16 + (lane & 15)) * 72 + (lane >> 4) * 8) * 2;
        #pragma unroll
        for (int kt = 0; kt < 4; ++kt) ldsm_x4(qah[kt], base + kt * 32);
    }
    __syncthreads();     // Q fully consumed; K area free for reuse

    auto issue = [&](int jt) {
        const int st = jt & 1, j0 = jt * 64;
        #pragma unroll
        for (int t = 0; t < 2; ++t) {   // K hi tile
            int idx = tid + t * 256;
            int r = idx >> 3, ch = idx & 7;
            cpa16(sb + G_K + st * G_KS + (r * 72 + ch * 8) * 2,
                  kg + (long)(j0 + r) * ND + ch * 8);
        }
        #pragma unroll
        for (int t = 0; t < 2; ++t) {   // V hi tile
            int idx = tid + t * 256;
            int d = idx >> 3, ch = idx & 7;
            cpa16(sb + G_V + st * G_KS + (d * 72 + ch * 8) * 2,
                  vtg + (long)d * NS + j0 + ch * 8);
        }
        if (j0 <= i0 + 127) {           // Pshift tile (fp32)
            #pragma unroll
            for (int t = 0; t < 8; ++t) {
                int idx = tid + t * 256;
                int r = idx >> 4, ch = idx & 15;
                cpa16(sb + G_P + st * G_PST + (r * 68 + ch * 4) * 4,
                      pg + (long)r * NS + j0 + ch * 4);
            }
        }
        cpa_commit();
    };

    issue(0);

    const int rA = wid * 16 + (lane >> 2);
    const int iA = i0 + rA, iB = iA + 8;
    const int miA = mask[b * NS + iA], miB = mask[b * NS + iB];
    const int brow = (lane & 7) | ((lane >> 1) & 8);
    const int bcol = ((lane >> 3) & 1) * 8;

    float oacc[8][4] = {};
    float mA = -1.0e30f, mB = -1.0e30f, lA = 0.0f, lB = 0.0f;

    for (int jt = 0; jt < 16; ++jt) {
        cpa_wait<0>();
        __syncthreads();
        if (jt + 1 < 16) issue(jt + 1);

        const int st = jt & 1, j0 = jt * 64;
        const uint32_t kb = sb + G_K + st * G_KS;
        const uint32_t vb = sb + G_V + st * G_KS;
        const bool anyP = (j0 <= i0 + 127);
        const float* psm = (const float*)(sm + G_P + st * G_PST);

        // ---- S = qh @ kh^T (1 MMA) ----
        float sacc[8][4] = {};
        #pragma unroll
        for (int kt = 0; kt < 4; ++kt) {
            uint32_t bhf[4][4];
            #pragma unroll
            for (int p = 0; p < 4; ++p)
                ldsm_x4(bhf[p], kb + ((p * 16 + brow) * 72 + bcol + kt * 16) * 2);
            #pragma unroll
            for (int nt = 0; nt < 8; ++nt)
                mma16<1>(sacc[nt], qah[kt], &bhf[nt >> 1][(nt & 1) * 2]);
        }

        // ---- logits (log2 domain): scale + pshift + mask ----
        #pragma unroll
        for (int nt = 0; nt < 8; ++nt) {
            int jl = nt * 8 + (lane & 3) * 2;
            int jg = j0 + jl;
            float p0A = 0, p1A = 0, p0B = 0, p1B = 0;
            if (anyP) {
                float2 fa = *(const float2*)(psm + rA * 68 + jl);
                float2 fb = *(const float2*)(psm + (rA + 8) * 68 + jl);
                p0A = (jg     <= iA) ? fa.x : 0.0f;
                p1A = (jg + 1 <= iA) ? fa.y : 0.0f;
                p0B = (jg     <= iB) ? fb.x : 0.0f;
                p1B = (jg + 1 <= iB) ? fb.y : 0.0f;
            }
            float b0 = mbias[jg], b1 = mbias[jg + 1];
            sacc[nt][0] = miA ? fmaf(sacc[nt][0], SC, p0A) + b0 : -1.0e9f;
            sacc[nt][1] = miA ? fmaf(sacc[nt][1], SC, p1A) + b1 : -1.0e9f;
            sacc[nt][2] = miB ? fmaf(sacc[nt][2], SC, p0B) + b0 : -1.0e9f;
            sacc[nt][3] = miB ? fmaf(sacc[nt][3], SC, p1B) + b1 : -1.0e9f;
        }

        // ---- online softmax (base-2, single-MUFU EX2) ----
        float rmA = -1.0e30f, rmB = -1.0e30f;
        #pragma unroll
        for (int nt = 0; nt < 8; ++nt) {
            rmA = fmaxf(rmA, fmaxf(sacc[nt][0], sacc[nt][1]));
            rmB = fmaxf(rmB, fmaxf(sacc[nt][2], sacc[nt][3]));
        }
        rmA = fmaxf(rmA, __shfl_xor_sync(0xffffffffu, rmA, 1));
        rmA = fmaxf(rmA, __shfl_xor_sync(0xffffffffu, rmA, 2));
        rmB = fmaxf(rmB, __shfl_xor_sync(0xffffffffu, rmB, 1));
        rmB = fmaxf(rmB, __shfl_xor_sync(0xffffffffu, rmB, 2));

        float mnA = fmaxf(mA, rmA), mnB = fmaxf(mB, rmB);
        float alA = fex2(mA - mnA), alB = fex2(mB - mnB);
        mA = mnA; mB = mnB;

        float rsA = 0.0f, rsB = 0.0f;
        #pragma unroll
        for (int nt = 0; nt < 8; ++nt) {
            sacc[nt][0] = fex2(sacc[nt][0] - mnA);
            sacc[nt][1] = fex2(sacc[nt][1] - mnA);
            sacc[nt][2] = fex2(sacc[nt][2] - mnB);
            sacc[nt][3] = fex2(sacc[nt][3] - mnB);
            rsA += sacc[nt][0] + sacc[nt][1];
            rsB += sacc[nt][2] + sacc[nt][3];
        }
        rsA += __shfl_xor_sync(0xffffffffu, rsA, 1);
        rsA += __shfl_xor_sync(0xffffffffu, rsA, 2);
        rsB += __shfl_xor_sync(0xffffffffu, rsB, 1);
        rsB += __shfl_xor_sync(0xffffffffu, rsB, 2);
        lA = lA * alA + rsA;
        lB = lB * alB + rsB;
        #pragma unroll
        for (int nt = 0; nt < 8; ++nt) {
            oacc[nt][0] *= alA; oacc[nt][1] *= alA;
            oacc[nt][2] *= alB; oacc[nt][3] *= alB;
        }

        // ---- pack P into fp16 A-fragments ----
        uint32_t pah[4][4];
        #pragma unroll
        for (int kt = 0; kt < 4; ++kt) {
            const float* e = sacc[2 * kt];
            const float* o = sacc[2 * kt + 1];
            pah[kt][0] = packhf(e[0], e[1]); pah[kt][1] = packhf(e[2], e[3]);
            pah[kt][2] = packhf(o[0], o[1]); pah[kt][3] = packhf(o[2], o[3]);
        }

        // ---- O += P @ Vh (1 MMA) ----
        #pragma unroll
        for (int kt = 0; kt < 4; ++kt) {
            uint32_t vhf[4][4];
            #pragma unroll
            for (int p = 0; p < 4; ++p)
                ldsm_x4(vhf[p], vb + ((p * 16 + brow) * 72 + bcol + kt * 16) * 2);
            #pragma unroll
            for (int nt = 0; nt < 8; ++nt)
                mma16<1>(oacc[nt], pah[kt], &vhf[nt >> 1][(nt & 1) * 2]);
        }
    }

    // ---- epilogue (lA/lB already fully reduced in-loop; NO extra shuffles) ----
    const float ivA = 1.0f / fmaxf(lA, 1e-30f);
    const float ivB = 1.0f / fmaxf(lB, 1e-30f);

    __syncthreads();     // other warps may still read stage smem
    __half* so = (__half*)sm;
    #pragma unroll
    for (int nt = 0; nt < 8; ++nt) {
        int c = nt * 8 + (lane & 3) * 2;
        *(__half2*)(so + rA * 72 + c) =
            __floats2half2_rn(oacc[nt][0] * ivA, oacc[nt][1] * ivA);
        *(__half2*)(so + (rA + 8) * 72 + c) =
            __floats2half2_rn(oacc[nt][2] * ivB, oacc[nt][3] * ivB);
    }
    __syncthreads();
    __half* cgb = ctx + (long)b * NS * ND + (long)i0 * ND + h * NDH;
    #pragma unroll
    for (int t = 0; t < 4; ++t) {
        int idx = tid + t * 256;
        int r = idx >> 3, ch = idx & 7;
        uint4 val = *(const uint4*)(so + r * 72 + ch * 8);
        *(uint4*)(cgb + (long)r * ND + ch * 8) = val;
    }
}

// ---------------------------------------------------------------------------
// Merged split: fp32 -> 16-bit hi/lo planes (bf16, or fp16 when f16[seg]=1)
// ---------------------------------------------------------------------------
struct SplitArgs {
    const float4* s[8];
    uint16_t* d[8];
    int n4[8];
    int f16[8];
};
__global__ void __launch_bounds__(256) split_all(SplitArgs a)
{
    const int seg = blockIdx.y;
    const int n4 = a.n4[seg];
    const float4* s = a.s[seg];
    uint16_t* dst = a.d[seg];
    const long pl = (long)n4 * 4;
    const bool f16 = a.f16[seg] != 0;
    for (int i = blockIdx.x * 256 + threadIdx.x; i < n4; i += gridDim.x * 256) {
        float4 x = s[i];
        uint32_t h0, h1, l0, l1;
        if (f16) {
            __half2 a0 = __floats2half2_rn(x.x, x.y);
            __half2 a1 = __floats2half2_rn(x.z, x.w);
            __half2 b0 = __floats2half2_rn(x.x - __half2float(__low2half(a0)),
                                           x.y - __half2float(__high2half(a0)));
            __half2 b1 = __floats2half2_rn(x.z - __half2float(__low2half(a1)),
                                           x.w - __half2float(__high2half(a1)));
            h0 = *(uint32_t*)&a0; h1 = *(uint32_t*)&a1;
            l0 = *(uint32_t*)&b0; l1 = *(uint32_t*)&b1;
        } else {
            __nv_bfloat162 a0 = __floats2bfloat162_rn(x.x, x.y);
            __nv_bfloat162 a1 = __floats2bfloat162_rn(x.z, x.w);
            __nv_bfloat162 b0 = __floats2bfloat162_rn(x.x - __low2float(a0),
                                                      x.y - __high2float(a0));
            __nv_bfloat162 b1 = __floats2bfloat162_rn(x.z - __low2float(a1),
                                                      x.w - __high2float(a1));
            h0 = *(uint32_t*)&a0; h1 = *(uint32_t*)&a1;
            l0 = *(uint32_t*)&b0; l1 = *(uint32_t*)&b1;
        }
        ((uint32_t*)dst)[2 * i]          = h0;
        ((uint32_t*)dst)[2 * i + 1]      = h1;
        ((uint32_t*)(dst + pl))[2 * i]     = l0;
        ((uint32_t*)(dst + pl))[2 * i + 1] = l1;
    }
}

// ---------------------------------------------------------------------------
extern "C" void kernel_launch(void* const* d_in, const int* in_sizes, int n_in,
                              void* d_out, int out_size)
{
    const float* query = (const float*)d_in[0];
    const float* key   = (const float*)d_in[1];
    const float* value = (const float*)d_in[2];
    const int*   mask  = (const int*)  d_in[3];
    const float* pe    = (const float*)d_in[4];
    const float* Wq    = (const float*)d_in[5];
    const float* Wk    = (const float*)d_in[6];
    const float* Wv    = (const float*)d_in[7];
    const float* Wo    = (const float*)d_in[8];
    float* out = (float*)d_out;

    void *vx, *vy, *vz, *vq, *vk, *vvt, *vctx, *vwq, *vwk, *vwv, *vwo,
         *vpe, *vps;
    cudaGetSymbolAddress(&vx, p_x);     cudaGetSymbolAddress(&vy, p_y);
    cudaGetSymbolAddress(&vz, p_z);     cudaGetSymbolAddress(&vq, p_q);
    cudaGetSymbolAddress(&vk, p_k);     cudaGetSymbolAddress(&vvt, p_vt);
    cudaGetSymbolAddress(&vctx, p_ctx);
    cudaGetSymbolAddress(&vwq, p_wq);   cudaGetSymbolAddress(&vwk, p_wk);
    cudaGetSymbolAddress(&vwv, p_wv);   cudaGetSymbolAddress(&vwo, p_wo);
    cudaGetSymbolAddress(&vpe, p_pe);   cudaGetSymbolAddress(&vps, g_pshift);

    SplitArgs sa;
    sa.s[0] = (const float4*)query; sa.d[0] = (uint16_t*)vx;  sa.n4[0] = (int)(E_X / 4);  sa.f16[0] = 0;
    sa.s[1] = (const float4*)key;   sa.d[1] = (uint16_t*)vy;  sa.n4[1] = (int)(E_X / 4);  sa.f16[1] = 0;
    sa.s[2] = (const float4*)value; sa.d[2] = (uint16_t*)vz;  sa.n4[2] = (int)(E_X / 4);  sa.f16[2] = 0;
    sa.s[3] = (const float4*)Wq;    sa.d[3] = (uint16_t*)vwq; sa.n4[3] = (int)(E_W / 4);  sa.f16[3] = 0;
    sa.s[4] = (const float4*)Wk;    sa.d[4] = (uint16_t*)vwk; sa.n4[4] = (int)(E_W / 4);  sa.f16[4] = 0;
    sa.s[5] = (const float4*)Wv;    sa.d[5] = (uint16_t*)vwv; sa.n4[5] = (int)(E_W / 4);  sa.f16[5] = 0;
    sa.s[6] = (const float4*)Wo;    sa.d[6] = (uint16_t*)vwo; sa.n4[6] = (int)(E_W / 4);  sa.f16[6] = 1;
    sa.s[7] = (const float4*)pe;    sa.d[7] = (uint16_t*)vpe; sa.n4[7] = (int)(E_PE / 4); sa.f16[7] = 1;
    split_all<<<dim3(1024, 8), 256>>>(sa);

    const int SM128 = 2 * (20480 + 2 * 128 * 80);  // 81920
    cudaFuncSetAttribute(gemm2<128, 0, 1, 1>, cudaFuncAttributeMaxDynamicSharedMemorySize, SM128);
    cudaFuncSetAttribute(gemm2<128, 2, 1, 0>, cudaFuncAttributeMaxDynamicSharedMemorySize, SM128);
    cudaFuncSetAttribute(gemm2<128, 6, 0, 0>, cudaFuncAttributeMaxDynamicSharedMemorySize, SM128);
    cudaFuncSetAttribute(fused_attn, cudaFuncAttributeMaxDynamicSharedMemorySize, G_TOT);

    const dim3 th(256);
    const long SD  = (long)NS * ND;
    const long SS  = (long)NS * NS;
    const long HSS = (long)NH * SS;

    // q,k,v projections merged: z<2 -> plane out (q,k); z==2 -> transposed vt
    const long dA = (long)(((char*)vy - (char*)vx) / 2);
    const long dB = (long)(((char*)vwk - (char*)vwq) / 2);
    const long dC = (long)(((char*)vk - (char*)vq) / 2);
    gemm2<128, 6, 0, 0><<<dim3(8, 32, 3), th, SM128>>>(
        vx, vwq, vq, vz, vwv, vvt,
        ND, ND, ND, ND,
        0, dA, 0, dB, 0, dC, E_X, E_W, E_X, 1.0f, 0);

    // Pshift = shifted (q @ pe^T) * 8 * log2e  (fp16 hi/lo 3-MMA, triangular)
    gemm2<128, 2, 1, 0><<<dim3(8, 8, NB * NH), th, SM128>>>(
        vq, vpe, vps, nullptr, nullptr, nullptr,
        NDH, ND, NDH, NS,
        SD, NDH, 0, (long)NS * NDH, HSS, SS, E_X, E_PE, 0, 8.0f * LOG2E, 1);

    // fused: QK^T + skew + mask + softmax + AV -> ctx (single fp16 plane)
    fused_attn<<<dim3(8, NB * NH), th, G_TOT>>>(
        (const __half*)vq, (const __half*)vk, (const __half*)vvt,
        (const float*)vps, mask, (__half*)vctx);

    // out = ctx(fp16, single plane) @ Wo(fp16 hi/lo)^T  -- 2-MMA
    gemm2<128, 0, 1, 1><<<dim3(8, 32, 1), th, SM128>>>(
        vctx, vwo, out, nullptr, nullptr, nullptr,
        ND, ND, ND, ND,
        0, 0, 0, 0, 0, 0, 0, E_W, 0, 1.0f, 0);
}